// round 16
// baseline (speedup 1.0000x reference)
#include <cuda_runtime.h>

// SobelLoss: loss = sum_{voxels,d in {x,y,z}} |conv_d(moved - label)| / (3*N)
// Shapes: (B=2, 1, D=160, H=192, W=160) fp32, zero padding.
// Sobel separable: S=[1,2,1] smooth, D=[-1,0,1] derivative.
// This version: each thread computes 4 output rows (2 packed row-pairs) x 1
// col, amortizing LDS + x-partials across pairs (9 LDS.64 / 4 outputs).
// Quad fetch slots (TILE_W=40), pair-packed smem, packed f32x2 math,
// NBUF=4, depth-2 A/B register prefetch, one barrier per two planes,
// ZCHUNK=16 -> 1200 CTAs @ 8/SM = one wave.

typedef unsigned long long ull;

#define DIMX 160
#define DIMY 192
#define DIMZ 160
#define NBATCH 2
#define PLANE (DIMY * DIMX)

#define TX 32
#define TY 4
#define NT (TX * TY)            // 128
#define OY 16                   // output rows per CTA (4 per thread)
#define ZCHUNK 16
#define NZCH (DIMZ / ZCHUNK)    // 10

#define TILE_W 40               // raw cols: gx in [32bx-4, 32bx+35], quad-aligned
#define NPAIR 10                // 20 raw rows as 10 (even,odd) pairs
#define PLANE_ULL (NPAIR * TILE_W)   // 400 ull per plane buffer
#define NQ 10                   // col quads per pair-row
#define NSLOT (NPAIR * NQ)      // 100 fetch slots (<= NT)
#define NBUF 4

#define GRID_X (DIMX / TX)      // 5
#define GRID_Y (DIMY / OY)      // 12
#define TOTAL_CTAS (GRID_X * GRID_Y * NBATCH * NZCH)   // 1200

// 1 / (3 * B*D*H*W) = 1 / 29491200
#define SCALE 3.3908420632258286e-08f
#define ABSM 0x7FFFFFFF7FFFFFFFULL

__device__ float    g_acc = 0.0f;
__device__ unsigned g_cnt = 0;

// ---- packed f32x2 helpers (Blackwell sm_103a) ----
__device__ __forceinline__ ull pk(float lo, float hi) {
    ull r; asm("mov.b64 %0, {%1, %2};" : "=l"(r) : "f"(lo), "f"(hi)); return r;
}
__device__ __forceinline__ void upk(ull p, float& lo, float& hi) {
    asm("mov.b64 {%0, %1}, %2;" : "=f"(lo), "=f"(hi) : "l"(p));
}
__device__ __forceinline__ ull padd(ull a, ull b) {
    ull r; asm("add.rn.f32x2 %0, %1, %2;" : "=l"(r) : "l"(a), "l"(b)); return r;
}
__device__ __forceinline__ ull pfma(ull a, ull b, ull c) {   // a*b + c
    ull r; asm("fma.rn.f32x2 %0, %1, %2, %3;" : "=l"(r) : "l"(a), "l"(b), "l"(c)); return r;
}
// (hi(a), lo(b))
__device__ __forceinline__ ull pmid(ull a, ull b) {
    float alo, ahi, blo, bhi;
    upk(a, alo, ahi); upk(b, blo, bhi);
    return pk(ahi, blo);
}

__launch_bounds__(NT, 8)   // <=64 regs -> 8 CTAs/SM -> 1200 grid = ONE wave
__global__ void sobel_loss_kernel(const float* __restrict__ moved,
                                  const float* __restrict__ label,
                                  float* __restrict__ out)
{
    // plane buffer: ull[pair][rawcol] = float2{ raw row 2*pair, raw row 2*pair+1 }
    __shared__ __align__(16) ull tile2[NBUF][PLANE_ULL];

    const int tx  = threadIdx.x;
    const int ty  = threadIdx.y;
    const int tid = ty * TX + tx;

    const int b  = blockIdx.z / NZCH;
    const int z0 = (blockIdx.z % NZCH) * ZCHUNK;   // multiple of 16 -> z0 & 3 == 0

    const int gy0 = blockIdx.y * OY - 1;   // global y of raw row 0
    const int gx0 = blockIdx.x * TX - 4;   // global x of raw col 0 (mult of 4)

    const float* mb = moved + (size_t)b * DIMZ * PLANE;
    const float* lb = label + (size_t)b * DIMZ * PLANE;

    const ull C2  = pk(2.0f, 2.0f);
    const ull CM1 = pk(-1.0f, -1.0f);

    // ---- fetch slot: (row pair, col quad) -> 2 rows x 4 cols per thread ----
    const int pair = tid / NQ;                  // 0..9 (tid < 100)
    const int q    = tid - pair * NQ;           // 0..9
    const int gx   = gx0 + 4 * q;               // mult of 4; quad fully in/out
    const int gyE  = gy0 + 2 * pair;
    const bool okx = (tid < NSLOT) && ((unsigned)gx < (unsigned)DIMX);
    const int offE = (okx && (unsigned)gyE       < (unsigned)DIMY) ? (gyE * DIMX + gx)       : -1;
    const int offO = (okx && (unsigned)(gyE + 1) < (unsigned)DIMY) ? ((gyE + 1) * DIMX + gx) : -1;
    const int wOff = pair * TILE_W + 4 * q;     // ull index; 32B aligned

    // two prefetch sets (A/B), 4 pair-packed cols each -> 2 planes in flight
    ull preA[4], preB[4];

    auto fetch = [&](int z, ull p[4]) {
        ulonglong2 mE = make_ulonglong2(0, 0), lE = mE, mO = mE, lO = mE;
        if ((unsigned)z < (unsigned)DIMZ) {
            const float* mz = mb + (size_t)z * PLANE;
            const float* lz = lb + (size_t)z * PLANE;
            if (offE >= 0) { mE = *(const ulonglong2*)(mz + offE); lE = *(const ulonglong2*)(lz + offE); }
            if (offO >= 0) { mO = *(const ulonglong2*)(mz + offO); lO = *(const ulonglong2*)(lz + offO); }
        }
        ull vE0 = pfma(lE.x, CM1, mE.x);   // diffs, cols 0-1 (even row)
        ull vE1 = pfma(lE.y, CM1, mE.y);   // cols 2-3
        ull vO0 = pfma(lO.x, CM1, mO.x);
        ull vO1 = pfma(lO.y, CM1, mO.y);
        float e0, e1, e2, e3, o0, o1, o2, o3;
        upk(vE0, e0, e1); upk(vE1, e2, e3);
        upk(vO0, o0, o1); upk(vO1, o2, o3);
        p[0] = pk(e0, o0); p[1] = pk(e1, o1);
        p[2] = pk(e2, o2); p[3] = pk(e3, o3);
    };

    auto store = [&](int buf, const ull p[4]) {
        if (tid < NSLOT) {
            *(ulonglong2*)&tile2[buf][wOff]     = make_ulonglong2(p[0], p[1]);
            *(ulonglong2*)&tile2[buf][wOff + 2] = make_ulonglong2(p[2], p[3]);
        }
    };

    // ---- packed in-plane partials for TWO output row-pairs at one col ----
    // output col tx (global 32bx+tx) -> raw local cols tx+3..tx+5
    // pairs 2ty, 2ty+1, 2ty+2 (raw rows 4ty .. 4ty+5)
    //   out pair A = rows 4ty+1,4ty+2 (from s/d pairs 0,1)
    //   out pair B = rows 4ty+3,4ty+4 (from s/d pairs 1,2)
    auto compute6 = [&](int buf,
                        ull& pA, ull& qA, ull& rA,
                        ull& pB, ull& qB, ull& rB) {
        const ull* b0 = &tile2[buf][(2 * ty) * TILE_W + tx + 3];
        ull a0 = b0[0],            c0 = b0[1],            e0 = b0[2];
        ull a1 = b0[TILE_W],       c1 = b0[TILE_W + 1],   e1 = b0[TILE_W + 2];
        ull a2 = b0[2 * TILE_W],   c2 = b0[2 * TILE_W + 1], e2 = b0[2 * TILE_W + 2];
        ull s0 = padd(pfma(c0, C2, a0), e0);
        ull d0 = pfma(a0, CM1, e0);
        ull s1 = padd(pfma(c1, C2, a1), e1);
        ull d1 = pfma(a1, CM1, e1);
        ull s2 = padd(pfma(c2, C2, a2), e2);
        ull d2 = pfma(a2, CM1, e2);
        qA = pfma(s0, CM1, s1);
        rA = padd(pfma(pmid(s0, s1), C2, s0), s1);
        pA = padd(pfma(pmid(d0, d1), C2, d0), d1);
        qB = pfma(s1, CM1, s2);
        rB = padd(pfma(pmid(s1, s2), C2, s1), s2);
        pB = padd(pfma(pmid(d1, d2), C2, d1), d2);
    };

    ull pA0,qA0,rA0, pA1,qA1,rA1, pB0,qB0,rB0, pB1,qB1,rB1;

    // ---- prologue: planes z0-1, z0, z0+1, z0+2 -> buf (relative j & 3) ----
    fetch(z0 - 1, preA); store(3, preA);   // j = -1 -> buf 3
    fetch(z0,     preA); store(0, preA);
    fetch(z0 + 1, preA); store(1, preA);
    fetch(z0 + 2, preA); store(2, preA);
    __syncthreads();

    compute6(3, pA0,qA0,rA0, pB0,qB0,rB0);   // plane z0-1
    compute6(0, pA1,qA1,rA1, pB1,qB1,rB1);   // plane z0

    fetch(z0 + 3, preA);   // stored at iter m=0
    fetch(z0 + 4, preB);   // stored at iter m=0

    ull accA = 0, accB = 0;

    // emit for one pair given its new partials (P2,Q2,R2), rolling regs inline
    #define EMITP(P0,P1,Q0,Q1,R0,R1, P2,Q2,R2, ACC)                        \
        do {                                                               \
            ull Gx = padd(pfma(P1, C2, P0), P2);                           \
            ull Gy = padd(pfma(Q1, C2, Q0), Q2);                           \
            ull Gz = pfma(R0, CM1, R2);                                    \
            ACC = padd(ACC, Gx & ABSM);                                    \
            ACC = padd(ACC, Gy & ABSM);                                    \
            ACC = padd(ACC, Gz & ABSM);                                    \
            P0 = P1; P1 = P2; Q0 = Q1; Q1 = Q2; R0 = R1; R1 = R2;          \
        } while (0)

    // ---- main loop: one barrier per TWO planes (R15 schedule) ----
    // iter m: barrier; store planes j=2m+3 (A), 2m+4 (B) over j=2m-1, 2m
    //   (read before this barrier); fetch j=2m+5, 2m+6;
    //   compute plane 2m+1 -> emit 2m; compute plane 2m+2 -> emit 2m+1.
    #pragma unroll 2
    for (int m = 0; m < ZCHUNK / 2; ++m) {
        __syncthreads();
        if (m < ZCHUNK / 2 - 1) {
            store((2 * m + 3) & 3, preA);
            store((2 * m + 4) & 3, preB);
        }
        if (m < ZCHUNK / 2 - 2) {
            fetch(z0 + 2 * m + 5, preA);
            fetch(z0 + 2 * m + 6, preB);
        }

        ull p2A,q2A,r2A, p2B,q2B,r2B;
        compute6((2 * m + 1) & 3, p2A,q2A,r2A, p2B,q2B,r2B);   // plane z0+2m+1
        EMITP(pA0,pA1,qA0,qA1,rA0,rA1, p2A,q2A,r2A, accA);      // emit z0+2m (pair A)
        EMITP(pB0,pB1,qB0,qB1,rB0,rB1, p2B,q2B,r2B, accB);      // emit z0+2m (pair B)

        compute6((2 * m + 2) & 3, p2A,q2A,r2A, p2B,q2B,r2B);   // plane z0+2m+2
        EMITP(pA0,pA1,qA0,qA1,rA0,rA1, p2A,q2A,r2A, accA);      // emit z0+2m+1
        EMITP(pB0,pB1,qB0,qB1,rB0,rB1, p2B,q2B,r2B, accB);
    }
    #undef EMITP

    // ---- reduce: packed -> scalar -> warp -> block -> global ----
    ull accT = padd(accA, accB);
    float lo, hi;
    upk(accT, lo, hi);
    float a = lo + hi;

    #pragma unroll
    for (int o = 16; o > 0; o >>= 1)
        a += __shfl_down_sync(0xFFFFFFFFu, a, o);

    __shared__ float wsum[NT / 32];
    if ((tid & 31) == 0) wsum[tid >> 5] = a;
    __syncthreads();

    if (tid < (NT / 32)) {
        float v = wsum[tid];
        #pragma unroll
        for (int o = (NT / 64); o > 0; o >>= 1)
            v += __shfl_down_sync(0xFu, v, o);
        if (tid == 0) {
            atomicAdd(&g_acc, v);
            __threadfence();
            if (atomicAdd(&g_cnt, 1u) == TOTAL_CTAS - 1) {
                __threadfence();
                *out = g_acc * SCALE;
                g_acc = 0.0f;      // reset for next (graph-replayed) launch
                g_cnt = 0;
            }
        }
    }
}

extern "C" void kernel_launch(void* const* d_in, const int* in_sizes, int n_in,
                              void* d_out, int out_size)
{
    const float* moved = (const float*)d_in[0];
    const float* label = (const float*)d_in[1];
    float* out = (float*)d_out;

    dim3 grid(GRID_X, GRID_Y, NBATCH * NZCH);   // (5, 12, 20) = 1200 CTAs
    dim3 block(TX, TY);                         // (32, 4)
    sobel_loss_kernel<<<grid, block>>>(moved, label, out);
}